// round 3
// baseline (speedup 1.0000x reference)
#include <cuda_runtime.h>
#include <cuda.h>
#include <math.h>

// QuadrotorDynamics: per-row map over (B,16) f32.
// Input row:  [0:3]=ang, [3:6]=pos(unused), [6:9]=rate, [9:12]=vel, [12:16]=cmd
// Output row: [0:3]=ang_dot, [3:6]=vel, [6:9]=rate_dot, [9:12]=vel_dot, [12:16]=0
//
// TMA (SW128) stages 256-row tiles into smem; compute threads read/write the
// swizzled layout conflict-free; TMA stores the tile back. The global side of
// the traffic rides the TMA pipe instead of the L1 LSU.

#define C_L      0.17f
#define C_MASS   0.68f
#define C_DARM   0.016f
#define C_KT     0.1f
#define C_KR     0.1f
#define C_IXX    0.007f
#define C_IYY    0.007f
#define C_IZZ    0.012f
#define C_GZ     9.8067f
#define C_707L   (0.707f * C_L)

// float4-index swizzle == TMA SWIZZLE_128B layout (verified: both map float4 j
// of 128B-row r to j ^ (r&7) within the row).
__device__ __forceinline__ int sw(int idx) { return idx ^ ((idx >> 3) & 7); }

__device__ __forceinline__ void compute_row(
    const float4 x0, const float4 x1, const float4 x2, const float4 x3,
    const float* __restrict__ ga, const float* __restrict__ gb, const float* __restrict__ gc,
    float4& o0, float4& o1, float4& o2)
{
    const float a0 = __ldg(&ga[0]), a1 = __ldg(&ga[1]), a2 = __ldg(&ga[2]), a3 = __ldg(&ga[3]);
    const float b0 = __ldg(&gb[0]), b1 = __ldg(&gb[1]), b2 = __ldg(&gb[2]), b3 = __ldg(&gb[3]);
    const float c0 = __ldg(&gc[0]), c1 = __ldg(&gc[1]), c2 = __ldg(&gc[2]), c3 = __ldg(&gc[3]);

    // thrusts = a*cmd^2 + b*cmd + c
    const float t0 = fmaf(fmaf(a0, x3.x, b0), x3.x, c0);
    const float t1 = fmaf(fmaf(a1, x3.y, b1), x3.y, c1);
    const float t2 = fmaf(fmaf(a2, x3.z, b2), x3.z, c2);
    const float t3 = fmaf(fmaf(a3, x3.w, b3), x3.w, c3);

    // torques = TORQUE_MAT @ thrusts (constants folded)
    const float tqT = t0 + t1 + t2 + t3;
    const float tq1 = C_707L * ((t0 + t3) - (t1 + t2));
    const float tq2 = C_707L * ((t2 + t3) - (t0 + t1));
    const float tq3 = C_DARM * ((t1 + t3) - (t0 + t2));

    float s_phi, c_phi, s_th, c_th, s_psi, c_psi;
    sincosf(x0.x, &s_phi, &c_phi);
    sincosf(x0.y, &s_th,  &c_th);
    sincosf(x0.z, &s_psi, &c_psi);

    const float p = x1.z, q = x1.w, r = x2.x;
    const float vx = x2.y, vy = x2.z, vz = x2.w;

    // ang_dot = inv(Mm) @ rate, closed form (det(Mm) = c_th)
    const float y2 = (s_phi * q + c_phi * r) / c_th;
    const float y1 = c_phi * q - s_phi * r;
    const float y0 = p + s_phi * y2;

    // rbi third column
    const float z0 = fmaf(c_phi * c_psi, s_th,  s_phi * s_psi);
    const float z1 = fmaf(c_phi * s_psi, s_th, -s_phi * c_psi);
    const float z2 = c_th * c_phi;

    // vel_dot = rbi[:,2]*(T/m) - KT*vel - GRAV
    const float Tm  = tqT * (1.0f / C_MASS);
    const float vd0 = fmaf(z0, Tm, -C_KT * vx);
    const float vd1 = fmaf(z1, Tm, -C_KT * vy);
    const float vd2 = fmaf(z2, Tm, -C_KT * vz) - C_GZ;

    // rate_dot = I_inv @ (tau - w x (I w) - KR*w)   (diagonal I)
    const float rd0 = (tq1 - q * r * (C_IZZ - C_IYY) - C_KR * p) * (1.0f / C_IXX);
    const float rd1 = (tq2 - r * p * (C_IXX - C_IZZ) - C_KR * q) * (1.0f / C_IYY);
    const float rd2 = (tq3 - p * q * (C_IYY - C_IXX) - C_KR * r) * (1.0f / C_IZZ);

    o0 = make_float4(y0,  y1,  y2,  vx);
    o1 = make_float4(vy,  vz,  rd0, rd1);
    o2 = make_float4(rd2, vd0, vd1, vd2);
}

// ---------------------------------------------------------------------------
// TMA kernel: full 256-row tiles via TMA; partial last tile via LDG fallback.
// ---------------------------------------------------------------------------
__global__ void __launch_bounds__(256)
quad_tma_kernel(const __grid_constant__ CUtensorMap tmap_in,
                const __grid_constant__ CUtensorMap tmap_out,
                const float4* __restrict__ in,
                float4* __restrict__ out,
                const float* __restrict__ ga,
                const float* __restrict__ gb,
                const float* __restrict__ gc,
                int n)
{
    __shared__ alignas(1024) float4 s[1024];   // 16 KB tile (256 rows)
    __shared__ uint64_t mbar;

    const int tid = threadIdx.x;
    const int row0 = blockIdx.x << 8;
    const int rows_here = min(256, n - row0);

    if (rows_here == 256) {
        // ---- TMA path (full tile) ----
        const unsigned smem_tile = (unsigned)__cvta_generic_to_shared(s);
        const unsigned smem_mbar = (unsigned)__cvta_generic_to_shared(&mbar);
        const int c1 = blockIdx.x << 7;        // 128B-row coordinate

        if (tid == 0) {
            asm volatile("mbarrier.init.shared.b64 [%0], 1;" :: "r"(smem_mbar) : "memory");
            asm volatile("fence.proxy.async.shared::cta;" ::: "memory");
        }
        __syncthreads();
        if (tid == 0) {
            asm volatile("mbarrier.arrive.expect_tx.shared.b64 _, [%0], %1;"
                         :: "r"(smem_mbar), "r"(16384u) : "memory");
            asm volatile("cp.async.bulk.tensor.2d.shared::cta.global.tile.mbarrier::complete_tx::bytes"
                         " [%0], [%1, {%2, %3}], [%4];"
                         :: "r"(smem_tile), "l"(&tmap_in), "r"(0), "r"(c1), "r"(smem_mbar)
                         : "memory");
        }
        // all threads wait for tile arrival (phase 0)
        {
            unsigned done = 0;
            do {
                asm volatile("{\n\t.reg .pred p;\n\t"
                             "mbarrier.try_wait.parity.acquire.cta.shared::cta.b64 p, [%1], %2;\n\t"
                             "selp.b32 %0, 1, 0, p;\n\t}"
                             : "=r"(done) : "r"(smem_mbar), "r"(0u) : "memory");
            } while (!done);
        }

        {
            const int i4 = tid << 2;
            const float4 x0 = s[sw(i4 + 0)];
            const float4 x1 = s[sw(i4 + 1)];
            const float4 x2 = s[sw(i4 + 2)];
            const float4 x3 = s[sw(i4 + 3)];
            float4 o0, o1, o2;
            compute_row(x0, x1, x2, x3, ga, gb, gc, o0, o1, o2);
            s[sw(i4 + 0)] = o0;
            s[sw(i4 + 1)] = o1;
            s[sw(i4 + 2)] = o2;
            s[sw(i4 + 3)] = make_float4(0.0f, 0.0f, 0.0f, 0.0f);
        }
        __syncthreads();

        if (tid == 0) {
            asm volatile("fence.proxy.async.shared::cta;" ::: "memory");
            asm volatile("cp.async.bulk.tensor.2d.global.shared::cta.tile.bulk_group"
                         " [%0, {%1, %2}], [%3];"
                         :: "l"(&tmap_out), "r"(0), "r"(c1), "r"(smem_tile)
                         : "memory");
            asm volatile("cp.async.bulk.commit_group;" ::: "memory");
            asm volatile("cp.async.bulk.wait_group.read 0;" ::: "memory");
        }
        __syncthreads();
    } else {
        // ---- fallback path (partial last tile): LDG/STS staging ----
        const int q_here = rows_here << 2;
        const int gbase = row0 << 2;

        #pragma unroll
        for (int k = 0; k < 4; k++) {
            int idx = tid + (k << 8);
            if (idx < q_here) s[sw(idx)] = in[gbase + idx];
        }
        __syncthreads();

        if (tid < rows_here) {
            const int i4 = tid << 2;
            const float4 x0 = s[sw(i4 + 0)];
            const float4 x1 = s[sw(i4 + 1)];
            const float4 x2 = s[sw(i4 + 2)];
            const float4 x3 = s[sw(i4 + 3)];
            float4 o0, o1, o2;
            compute_row(x0, x1, x2, x3, ga, gb, gc, o0, o1, o2);
            s[sw(i4 + 0)] = o0;
            s[sw(i4 + 1)] = o1;
            s[sw(i4 + 2)] = o2;
            s[sw(i4 + 3)] = make_float4(0.0f, 0.0f, 0.0f, 0.0f);
        }
        __syncthreads();

        #pragma unroll
        for (int k = 0; k < 4; k++) {
            int idx = tid + (k << 8);
            if (idx < q_here) out[gbase + idx] = s[sw(idx)];
        }
    }
}

// ---------------------------------------------------------------------------
// Non-TMA kernel (used only if driver entry point is unavailable).
// ---------------------------------------------------------------------------
__global__ void __launch_bounds__(256)
quad_dyn_kernel(const float4* __restrict__ in,
                float4* __restrict__ out,
                const float* __restrict__ ga,
                const float* __restrict__ gb,
                const float* __restrict__ gc,
                int n)
{
    __shared__ float4 s[1024];
    const int tid = threadIdx.x;
    const int row0 = blockIdx.x << 8;
    const int rows_here = min(256, n - row0);
    const int q_here = rows_here << 2;
    const int gbase = row0 << 2;

    #pragma unroll
    for (int k = 0; k < 4; k++) {
        int idx = tid + (k << 8);
        if (idx < q_here) s[sw(idx)] = in[gbase + idx];
    }
    __syncthreads();

    if (tid < rows_here) {
        const int i4 = tid << 2;
        const float4 x0 = s[sw(i4 + 0)];
        const float4 x1 = s[sw(i4 + 1)];
        const float4 x2 = s[sw(i4 + 2)];
        const float4 x3 = s[sw(i4 + 3)];
        float4 o0, o1, o2;
        compute_row(x0, x1, x2, x3, ga, gb, gc, o0, o1, o2);
        s[sw(i4 + 0)] = o0;
        s[sw(i4 + 1)] = o1;
        s[sw(i4 + 2)] = o2;
        s[sw(i4 + 3)] = make_float4(0.0f, 0.0f, 0.0f, 0.0f);
    }
    __syncthreads();

    #pragma unroll
    for (int k = 0; k < 4; k++) {
        int idx = tid + (k << 8);
        if (idx < q_here) out[gbase + idx] = s[sw(idx)];
    }
}

// ---------------------------------------------------------------------------
// Host side
// ---------------------------------------------------------------------------
typedef CUresult (*EncodeTiledFn)(
    CUtensorMap*, CUtensorMapDataType, cuuint32_t, void*,
    const cuuint64_t*, const cuuint64_t*, const cuuint32_t*, const cuuint32_t*,
    CUtensorMapInterleave, CUtensorMapSwizzle, CUtensorMapL2promotion,
    CUtensorMapFloatOOBfill);

static bool build_map(EncodeTiledFn enc, CUtensorMap* m, void* ptr,
                      unsigned long long rows128)
{
    cuuint64_t dims[2]    = {32ull, rows128};    // 32 f32 (128B) x rows
    cuuint64_t strides[1] = {128ull};            // bytes between rows
    cuuint32_t box[2]     = {32u, 128u};         // 128B x 128 rows = 16 KB tile
    cuuint32_t es[2]      = {1u, 1u};
    CUresult r = enc(m, CU_TENSOR_MAP_DATA_TYPE_FLOAT32, 2, ptr,
                     dims, strides, box, es,
                     CU_TENSOR_MAP_INTERLEAVE_NONE,
                     CU_TENSOR_MAP_SWIZZLE_128B,
                     CU_TENSOR_MAP_L2_PROMOTION_L2_128B,
                     CU_TENSOR_MAP_FLOAT_OOB_FILL_NONE);
    return r == CUDA_SUCCESS;
}

extern "C" void kernel_launch(void* const* d_in, const int* in_sizes, int n_in,
                              void* d_out, int out_size)
{
    // metadata order: t (scalar, unused), input (B*16 f32), a(4), b(4), c(4)
    const float4* in = (const float4*)d_in[1];
    const float*  a  = (const float*)d_in[2];
    const float*  b  = (const float*)d_in[3];
    const float*  c  = (const float*)d_in[4];
    float4* out = (float4*)d_out;

    const int n = in_sizes[1] / 16;                 // rows
    const unsigned long long rows128 = (unsigned long long)in_sizes[1] / 32ull;
    const int threads = 256;
    const int blocks = (n + threads - 1) / threads; // 256 rows per block

    EncodeTiledFn enc = nullptr;
    cudaDriverEntryPointQueryResult qs;
    void* fn = nullptr;
    if (cudaGetDriverEntryPoint("cuTensorMapEncodeTiled", &fn,
                                cudaEnableDefault, &qs) == cudaSuccess &&
        qs == cudaDriverEntryPointSuccess && fn) {
        enc = (EncodeTiledFn)fn;
    }

    if (enc) {
        CUtensorMap tin, tout;
        bool ok = build_map(enc, &tin,  (void*)d_in[1], rows128);
        ok     &= build_map(enc, &tout, (void*)d_out,   rows128);
        if (ok) {
            quad_tma_kernel<<<blocks, threads>>>(tin, tout, in, out, a, b, c, n);
            return;
        }
    }
    quad_dyn_kernel<<<blocks, threads>>>(in, out, a, b, c, n);
}